// round 2
// baseline (speedup 1.0000x reference)
#include <cuda_runtime.h>
#include <cstdint>

#define T_STEPS 64
#define BB      8
#define IN_DIM  256
#define HH      512
#define H3      1536
#define NBLK    128
#define NTHR    256

// ---------------- output offsets (floats) ----------------
#define OUT_V      0ull
#define OUT_H      4096ull
#define OUT_DUF    8192ull
#define OUT_TEF    2105344ull
#define OUT_TEMAT  2109440ull
#define OUT_OUTS   4206592ull
#define OUT_DUS    4468736ull
#define OUT_MODS   138686464ull
#define OUT_SS     138735616ull
#define OUT_MS     138736128ull
#define OUT_RS     138736640ull

// ---------------- smem layout (float index) ----------------
#define S_H    0
#define S_HFW  4096
#define S_TEO  8192
#define S_PRE  12288
#define S_NH   13824
#define S_MOD  14336
#define S_SCAL 14464   /* trace: s[0..7], m[8..15] */
#define S_BT   14480   /* batch: r,s,m */
#define S_FW   14496   /* fw[il*8+b], 32 */
#define S_FWP  14528   /* fw partials [32][8] */
#define S_RED  14784   /* reductions [8] */
#define S_TOTF 14856
// prologue scratch overlays [0..14848): sX[1024] + wtile[1536*9]

// ---------------- device globals ----------------
__device__ float    g_wx[T_STEPS * BB * H3];
__device__ float    g_wh[BB * H3];
__device__ float    g_h[BB * HH];
__device__ float    g_hfw[BB * HH];
__device__ float    g_te1[BB * HH];
__device__ float    g_sm[16];
__device__ unsigned g_ctr[2];   // [0]=cA (trace+W done), [1]=cB (batch done)

// ---------------- helpers ----------------
__device__ __forceinline__ unsigned ld_acq(const unsigned* p) {
    unsigned v;
    asm volatile("ld.global.acquire.gpu.b32 %0, [%1];" : "=r"(v) : "l"(p) : "memory");
    return v;
}
__device__ __forceinline__ void wait_ge(unsigned* p, unsigned tgt) {
    if (threadIdx.x == 0) {
        while (ld_acq(p) < tgt) __nanosleep(40);
    }
    __syncthreads();
}
__device__ __forceinline__ void publish(unsigned* p) {
    __syncthreads();
    if (threadIdx.x == 0) {
        __threadfence();
        atomicAdd(p, 1u);
    }
}
__device__ __forceinline__ float sigm(float x) { return 1.f / (1.f + expf(-x)); }

__device__ __forceinline__ float block_sum(float v, float* sRed) {
#pragma unroll
    for (int o = 16; o; o >>= 1) v += __shfl_down_sync(0xffffffffu, v, o);
    __syncthreads();
    if ((threadIdx.x & 31) == 0) sRed[threadIdx.x >> 5] = v;
    __syncthreads();
    float a = 0.f;
#pragma unroll
    for (int w = 0; w < 8; w++) a += sRed[w];
    return a;
}

__global__ void zero_ctrs_kernel() {
    if (threadIdx.x < 2) g_ctr[threadIdx.x] = 0u;
}

// ====================================================================
__global__ void __launch_bounds__(NTHR, 1)
sgru_main(const float* __restrict__ x,       const float* __restrict__ h_in,
          const float* __restrict__ v_in,    const float* __restrict__ dU_in,
          const float* __restrict__ te_in,   const float* __restrict__ tE_in,
          const float* __restrict__ x2h_w,   const float* __restrict__ x2h_b,
          const float* __restrict__ h2h_w,   const float* __restrict__ h2h_b,
          const float* __restrict__ lnx_g,   const float* __restrict__ lnx_b,
          const float* __restrict__ lnh_g,   const float* __restrict__ lnh_b,
          const float* __restrict__ h2mod_w, const float* __restrict__ h2mod_b,
          const float* __restrict__ m2r_w,   const float* __restrict__ m2r_b,
          const float* __restrict__ m2s_w,   const float* __restrict__ m2s_b,
          const float* __restrict__ m2m_w,   const float* __restrict__ m2m_b,
          const float* __restrict__ alpha_p, const float* __restrict__ tauU_p,
          float* __restrict__ out)
{
    extern __shared__ float sm[];
    const int tid = threadIdx.x;
    const int bk  = blockIdx.x;
    const int wid = tid >> 5, lid = tid & 31;
    const int i0  = bk * 4;
    const int j0  = 2 * tid;

    float* sH    = sm + S_H;
    float* sHfw  = sm + S_HFW;
    float* sTeo  = sm + S_TEO;
    float* sPre  = sm + S_PRE;
    float* sNH   = sm + S_NH;
    float* sMod  = sm + S_MOD;
    float* sScal = sm + S_SCAL;
    float* sBt   = sm + S_BT;
    float* sFw   = sm + S_FW;
    float* sFwP  = sm + S_FWP;
    float* sRed  = sm + S_RED;

    const float spa     = log1pf(expf(alpha_p[0]));
    const float inv_spe = 1.f / (spa + 1e-8f);
    const float tau     = sigm(tauU_p[0]);
    const float omtau   = 1.f - tau;

    float* tebuf0 = out + OUT_TEF;   // te parity-0 buffer == final te output
    float* tebuf1 = g_te1;

    // ================= PROLOGUE: Wx = LN(x @ x2h^T + b) =================
    {
        float* sX    = sm;           // [4][256]
        float* wtile = sm + 1024;    // [1536][9] padded
        const int rg0 = bk * 4;      // rows rg0..rg0+3 of (T*B, H3)

        float acc[4][6];
#pragma unroll
        for (int r = 0; r < 4; r++)
#pragma unroll
            for (int q = 0; q < 6; q++) acc[r][q] = 0.f;

        for (int idx = tid; idx < 4 * IN_DIM; idx += NTHR)
            sX[idx] = x[(size_t)rg0 * IN_DIM + idx];

        for (int ct = 0; ct < 32; ++ct) {
            const int c0 = ct * 8;
            __syncthreads();
            for (int idx = tid; idx < H3 * 8; idx += NTHR) {
                int kl = idx >> 3, c = idx & 7;
                wtile[kl * 9 + c] = x2h_w[(size_t)kl * IN_DIM + c0 + c];
            }
            __syncthreads();
            float xv[4][8];
#pragma unroll
            for (int r = 0; r < 4; r++)
#pragma unroll
                for (int c = 0; c < 8; c++) xv[r][c] = sX[r * IN_DIM + c0 + c];
#pragma unroll
            for (int q = 0; q < 6; q++) {
                const int kk = tid + 256 * q;
                float wv[8];
#pragma unroll
                for (int c = 0; c < 8; c++) wv[c] = wtile[kk * 9 + c];
#pragma unroll
                for (int r = 0; r < 4; r++)
#pragma unroll
                    for (int c = 0; c < 8; c++)
                        acc[r][q] = fmaf(wv[c], xv[r][c], acc[r][q]);
            }
        }
        // bias
        float bq[6], lg[6], lb[6];
#pragma unroll
        for (int q = 0; q < 6; q++) {
            int kk = tid + 256 * q;
            bq[q] = x2h_b[kk]; lg[q] = lnx_g[kk]; lb[q] = lnx_b[kk];
        }
#pragma unroll
        for (int r = 0; r < 4; r++)
#pragma unroll
            for (int q = 0; q < 6; q++) acc[r][q] += bq[q];
        // LN per row + store
#pragma unroll
        for (int r = 0; r < 4; r++) {
            float s1 = 0.f, s2 = 0.f;
#pragma unroll
            for (int q = 0; q < 6; q++) { float v = acc[r][q]; s1 += v; s2 = fmaf(v, v, s2); }
            s1 = block_sum(s1, sRed);
            s2 = block_sum(s2, sRed);
            const float mu   = s1 * (1.f / H3);
            const float rstd = rsqrtf(s2 * (1.f / H3) - mu * mu + 1e-5f);
            float* wrow = g_wx + (size_t)(rg0 + r) * H3;
#pragma unroll
            for (int q = 0; q < 6; q++) {
                int kk = tid + 256 * q;
                wrow[kk] = (acc[r][q] - mu) * rstd * lg[q] + lb[q];
            }
        }
        __syncthreads();
    }

    // ================= PROLOGUE: persistent state =================
    float rTE[64], rDU[64], rUp[8], rLo[8];
#pragma unroll
    for (int il = 0; il < 4; ++il) {
        const float* wr = h2h_w + (size_t)(2 * HH + i0 + il) * HH;
        float2 w2 = *(const float2*)&wr[j0];
        rUp[il * 2 + 0] =  fmaxf(1.f - w2.x, 0.f) * inv_spe;
        rUp[il * 2 + 1] =  fmaxf(1.f - w2.y, 0.f) * inv_spe;
        rLo[il * 2 + 0] = -fmaxf(1.f + w2.x, 0.f) * inv_spe;
        rLo[il * 2 + 1] = -fmaxf(1.f + w2.y, 0.f) * inv_spe;
#pragma unroll
        for (int b = 0; b < 8; b++) {
            const int row = il * 8 + b;
            const size_t g = ((size_t)(b * HH + i0 + il)) * HH + j0;
            float2 t2 = *(const float2*)&tE_in[g];
            float2 d2 = *(const float2*)&dU_in[g];
            rTE[row * 2] = t2.x; rTE[row * 2 + 1] = t2.y;
            rDU[row * 2] = d2.x; rDU[row * 2 + 1] = d2.y;
        }
    }
    for (int idx = tid; idx < BB * HH; idx += NTHR) sH[idx] = h_in[idx];

    float vreg0 = 0.f, vreg1 = 0.f;
    if (bk < BB) {
        vreg0 = v_in[bk * HH + tid];
        vreg1 = v_in[bk * HH + tid + 256];
        tebuf0[bk * HH + tid]       = te_in[bk * HH + tid];
        tebuf0[bk * HH + tid + 256] = te_in[bk * HH + tid + 256];
    }
    __syncthreads();

    // fw_0 = spa * dU_init . h_0 (own rows)
#pragma unroll
    for (int b = 0; b < 8; b++) {
        float2 hh = *(float2*)&sH[b * HH + j0];
#pragma unroll
        for (int il = 0; il < 4; ++il) {
            const int row = il * 8 + b;
            float fwp = rDU[row * 2] * hh.x + rDU[row * 2 + 1] * hh.y;
#pragma unroll
            for (int o = 16; o; o >>= 1) fwp += __shfl_down_sync(0xffffffffu, fwp, o);
            if (lid == 0) sFwP[row * 8 + wid] = fwp;
        }
    }
    __syncthreads();
    if (tid < 32) {
        float a = 0.f;
#pragma unroll
        for (int w = 0; w < 8; w++) a += sFwP[tid * 8 + w];
        sFw[tid] = spa * a;
    }
    __syncthreads();

    // ================= MAIN LOOP =================
    for (int it = 0; it <= T_STEPS; ++it) {
        if (it > 0) {
            wait_ge(&g_ctr[1], 8u * (unsigned)it);
            const float* teo_g = ((it - 1) & 1) ? tebuf1 : tebuf0;
            for (int idx = tid; idx < BB * HH; idx += NTHR) {
                sH[idx]   = __ldcg(&g_h[idx]);
                sHfw[idx] = __ldcg(&g_hfw[idx]);
                sTeo[idx] = __ldcg(&teo_g[idx]);
            }
            if (tid < 16) sScal[tid] = __ldcg(&g_sm[tid]);
            __syncthreads();

            // ---- trace update for step it-1 (tE, dU regs) + fw for step it ----
            float* dus = out + OUT_DUS + (size_t)(it - 1) * (BB * HH * HH);
#pragma unroll
            for (int b = 0; b < 8; b++) {
                const float sb  = sScal[b];
                const float mb  = sScal[8 + b];
                const float oms = 1.f - sb;
                const float tm  = tau * mb;
                float2 teo = *(float2*)&sTeo[b * HH + j0];
                float2 hf  = *(float2*)&sHfw[b * HH + j0];
                float2 hh  = *(float2*)&sH  [b * HH + j0];
#pragma unroll
                for (int il = 0; il < 4; ++il) {
                    const int row = il * 8 + b;
                    const float hfi = sHfw[b * HH + i0 + il];
                    const float tei = sTeo[b * HH + i0 + il];
                    float o0 = hfi * teo.x - tei * hf.x;
                    float o1 = hfi * teo.y - tei * hf.y;
                    float t0 = oms * rTE[row * 2]     + sb * o0;
                    float t1 = oms * rTE[row * 2 + 1] + sb * o1;
                    rTE[row * 2] = t0; rTE[row * 2 + 1] = t1;
                    float d0 = omtau * rDU[row * 2]     + tm * t0;
                    float d1 = omtau * rDU[row * 2 + 1] + tm * t1;
                    d0 = fminf(d0, rUp[il * 2]);     d0 = fmaxf(d0, rLo[il * 2]);
                    d1 = fminf(d1, rUp[il * 2 + 1]); d1 = fmaxf(d1, rLo[il * 2 + 1]);
                    rDU[row * 2] = d0; rDU[row * 2 + 1] = d1;
                    *(float2*)&dus[((size_t)(b * HH + i0 + il)) * HH + j0] = make_float2(d0, d1);
                    float fwp = d0 * hh.x + d1 * hh.y;
#pragma unroll
                    for (int o = 16; o; o >>= 1) fwp += __shfl_down_sync(0xffffffffu, fwp, o);
                    if (lid == 0) sFwP[row * 8 + wid] = fwp;
                }
            }
            __syncthreads();
            if (tid < 32) {
                float a = 0.f;
#pragma unroll
                for (int w = 0; w < 8; w++) a += sFwP[tid * 8 + w];
                sFw[tid] = spa * a;
            }
            __syncthreads();
        }

        if (it < T_STEPS) {
            // ---- W phase: Whraw rows (12 per block) ----
#pragma unroll
            for (int rep = 0; rep < 2; rep++) {
                const int ridx = wid + rep * 8;
                if (ridx < 12) {
                    const bool isB = (ridx >= 8);
                    const int  il  = ridx - 8;
                    const int  k   = isB ? (2 * HH + bk * 4 + il) : (bk * 8 + ridx);
                    const float2* wrow = (const float2*)(h2h_w + (size_t)k * HH);
                    float2 wv[8];
#pragma unroll
                    for (int c = 0; c < 8; c++) wv[c] = wrow[lid + 32 * c];
                    float acc[8];
#pragma unroll
                    for (int b = 0; b < 8; b++) acc[b] = 0.f;
#pragma unroll
                    for (int c = 0; c < 8; c++) {
                        const int jj = 2 * (lid + 32 * c);
#pragma unroll
                        for (int b = 0; b < 8; b++) {
                            float2 hv = *(float2*)&sH[b * HH + jj];
                            acc[b] = fmaf(wv[c].x, hv.x, acc[b]);
                            acc[b] = fmaf(wv[c].y, hv.y, acc[b]);
                        }
                    }
                    const float bias = h2h_b[k];
#pragma unroll
                    for (int b = 0; b < 8; b++) {
                        float v = acc[b];
#pragma unroll
                        for (int o = 16; o; o >>= 1) v += __shfl_xor_sync(0xffffffffu, v, o);
                        if (lid == b) {
                            float add = bias + (isB ? sFw[il * 8 + b] : 0.f);
                            g_wh[b * H3 + k] = v + add;
                        }
                    }
                }
            }
            publish(&g_ctr[0]);

            // ---- batch phase (blocks 0..7, block b = bk) ----
            if (bk < BB) {
                wait_ge(&g_ctr[0], (unsigned)NBLK * (unsigned)(it + 1));
                const int b = bk;
                float whv[6];
                float s1 = 0.f, s2 = 0.f;
#pragma unroll
                for (int q = 0; q < 6; q++) {
                    float v = __ldcg(&g_wh[b * H3 + tid + 256 * q]);
                    whv[q] = v; s1 += v; s2 = fmaf(v, v, s2);
                }
                s1 = block_sum(s1, sRed);
                s2 = block_sum(s2, sRed);
                const float mu   = s1 * (1.f / H3);
                const float rstd = rsqrtf(s2 * (1.f / H3) - mu * mu + 1e-5f);
                const float* wxr = g_wx + (size_t)(it * BB + b) * H3;
#pragma unroll
                for (int q = 0; q < 6; q++) {
                    const int kk = tid + 256 * q;
                    sPre[kk] = (whv[q] - mu) * rstd * lnh_g[kk] + lnh_b[kk] + wxr[kk];
                }
                __syncthreads();
                // gates + v + new_h + hfw
                float hf_e[2];
#pragma unroll
                for (int e = 0; e < 2; e++) {
                    const int j = tid + 256 * e;
                    const float z  = sigm(sPre[j]);
                    const float o  = sigm(sPre[HH + j]);
                    const float dv = sPre[2 * HH + j];
                    float* vr = e ? &vreg1 : &vreg0;
                    *vr = (1.f - z) * (*vr) + z * dv;
                    const float nh = fmaxf(*vr, 0.f);
                    hf_e[e] = o * nh;
                    sNH[j] = nh;
                    g_h[b * HH + j]   = nh;
                    g_hfw[b * HH + j] = hf_e[e];
                    out[OUT_OUTS + (size_t)it * (BB * HH) + b * HH + j] = nh;
                }
                __syncthreads();
                // mod = relu(new_h @ h2mod^T + b): 96 rows
#pragma unroll
                for (int rep = 0; rep < 12; rep++) {
                    const int row = wid + 8 * rep;
                    const float2* mw = (const float2*)(h2mod_w + (size_t)row * HH);
                    float a = 0.f;
#pragma unroll
                    for (int c = 0; c < 8; c++) {
                        float2 w2 = mw[lid + 32 * c];
                        float2 h2 = *(float2*)&sNH[2 * (lid + 32 * c)];
                        a = fmaf(w2.x, h2.x, a);
                        a = fmaf(w2.y, h2.y, a);
                    }
#pragma unroll
                    for (int o = 16; o; o >>= 1) a += __shfl_xor_sync(0xffffffffu, a, o);
                    if (lid == 0) {
                        const float mv = fmaxf(a + h2mod_b[row], 0.f);
                        sMod[row] = mv;
                        out[OUT_MODS + (size_t)it * (BB * 96) + b * 96 + row] = mv;
                    }
                }
                __syncthreads();
                // scalars r, s, m
                if (wid < 3) {
                    const float* ww = (wid == 0) ? m2r_w : (wid == 1) ? m2s_w : m2m_w;
                    float a = sMod[wid * 32 + lid] * ww[lid];
#pragma unroll
                    for (int o = 16; o; o >>= 1) a += __shfl_xor_sync(0xffffffffu, a, o);
                    if (lid == 0) {
                        if (wid == 0) {
                            const float r = sigm(a + m2r_b[0]);
                            sBt[0] = r;
                            out[OUT_RS + (size_t)it * BB + b] = r;
                        } else if (wid == 1) {
                            const float s = sigm(a + m2s_b[0]);
                            sBt[1] = s; g_sm[b] = s;
                            out[OUT_SS + (size_t)it * BB + b] = s;
                        } else {
                            const float mmv = a + m2m_b[0];
                            const float m = mmv - tanhf(mmv);
                            sBt[2] = m; g_sm[8 + b] = m;
                            out[OUT_MS + (size_t)it * BB + b] = m;
                        }
                    }
                }
                __syncthreads();
                const float r = sBt[0];
                float* tob = (it & 1) ? tebuf1 : tebuf0;
                float* tnb = (it & 1) ? tebuf0 : tebuf1;
#pragma unroll
                for (int e = 0; e < 2; e++) {
                    const int j = tid + 256 * e;
                    const float to = __ldcg(&tob[b * HH + j]);
                    tnb[b * HH + j] = (1.f - r) * to + r * hf_e[e];
                }
                publish(&g_ctr[1]);
            }
        }
    }

    // ================= EPILOGUE =================
#pragma unroll
    for (int il = 0; il < 4; ++il)
#pragma unroll
        for (int b = 0; b < 8; b++) {
            const int row = il * 8 + b;
            const size_t g = ((size_t)(b * HH + i0 + il)) * HH + j0;
            *(float2*)&out[OUT_TEMAT + g] = make_float2(rTE[row * 2], rTE[row * 2 + 1]);
            *(float2*)&out[OUT_DUF  + g] = make_float2(rDU[row * 2], rDU[row * 2 + 1]);
        }
    if (bk < BB) {
        out[OUT_V + bk * HH + tid]       = vreg0;
        out[OUT_V + bk * HH + tid + 256] = vreg1;
        out[OUT_H + bk * HH + tid]       = sH[bk * HH + tid];
        out[OUT_H + bk * HH + tid + 256] = sH[bk * HH + tid + 256];
    }
}

// ====================================================================
extern "C" void kernel_launch(void* const* d_in, const int* in_sizes, int n_in,
                              void* d_out, int out_size) {
    const float* x       = (const float*)d_in[0];
    const float* h       = (const float*)d_in[1];
    const float* v       = (const float*)d_in[2];
    const float* dU      = (const float*)d_in[3];
    const float* te      = (const float*)d_in[4];
    const float* tE      = (const float*)d_in[5];
    const float* x2h_w   = (const float*)d_in[6];
    const float* x2h_b   = (const float*)d_in[7];
    const float* h2h_w   = (const float*)d_in[8];
    const float* h2h_b   = (const float*)d_in[9];
    const float* lnx_g   = (const float*)d_in[10];
    const float* lnx_b   = (const float*)d_in[11];
    const float* lnh_g   = (const float*)d_in[12];
    const float* lnh_b   = (const float*)d_in[13];
    const float* h2mod_w = (const float*)d_in[14];
    const float* h2mod_b = (const float*)d_in[15];
    const float* m2r_w   = (const float*)d_in[16];
    const float* m2r_b   = (const float*)d_in[17];
    const float* m2s_w   = (const float*)d_in[18];
    const float* m2s_b   = (const float*)d_in[19];
    const float* m2m_w   = (const float*)d_in[20];
    const float* m2m_b   = (const float*)d_in[21];
    const float* alpha   = (const float*)d_in[22];
    const float* tauU    = (const float*)d_in[23];
    float* out = (float*)d_out;

    const size_t smem = (size_t)S_TOTF * sizeof(float);
    cudaFuncSetAttribute(sgru_main, cudaFuncAttributeMaxDynamicSharedMemorySize, (int)smem);

    zero_ctrs_kernel<<<1, 32>>>();
    sgru_main<<<NBLK, NTHR, smem>>>(x, h, v, dU, te, tE,
                                    x2h_w, x2h_b, h2h_w, h2h_b,
                                    lnx_g, lnx_b, lnh_g, lnh_b,
                                    h2mod_w, h2mod_b,
                                    m2r_w, m2r_b, m2s_w, m2s_b, m2m_w, m2m_b,
                                    alpha, tauU, out);
}